// round 6
// baseline (speedup 1.0000x reference)
#include <cuda_runtime.h>
#include <cuda_bf16.h>
#include <cstdint>
#include <math.h>

#define B_ 512
#define S_ 200
#define H_ 512
#define A_ 32
#define M_ (B_*S_)          // 102400 rows
#define NEGV (-1e9f)

// ---------------- device scratch (no allocations allowed) ----------------
__device__ float g_moe[(M_ + 64) * H_];       // ~210MB
__device__ __nv_bfloat16 g_Ah0[M_ * H_];      // bf16(item+pos)  105MB
__device__ __nv_bfloat16 g_Ah1[M_ * H_];      // bf16(item)      105MB
__device__ float g_w[M_];                     // attention logits -> tma softmax
__device__ float g_bij[M_ * A_];
__device__ float g_awT[H_ * A_];
__device__ __nv_bfloat16 g_wTh[H_ * H_];      // transposed weight bf16 [n][k]
__device__ int   g_count[B_ * A_];
__device__ float g_dummy_gates[M_ * A_];
__device__ float g_dummy_mask[B_ * A_];

// ---------------- PTX helpers (family-portable) ----------------
__device__ __forceinline__ uint32_t pk_bf16x2(float x, float y) {
    __nv_bfloat162 t = __float22bfloat162_rn(make_float2(x, y));
    return *(uint32_t*)&t;
}
__device__ __forceinline__ uint32_t smem_u32(const void* p) {
    uint32_t a;
    asm("{ .reg .u64 t; cvta.to.shared.u64 t, %1; cvt.u32.u64 %0, t; }" : "=r"(a) : "l"(p));
    return a;
}
__device__ __forceinline__ void ldm4(uint32_t r[4], uint32_t addr) {
    asm volatile("ldmatrix.sync.aligned.m8n8.x4.shared.b16 {%0,%1,%2,%3}, [%4];"
                 : "=r"(r[0]), "=r"(r[1]), "=r"(r[2]), "=r"(r[3]) : "r"(addr));
}
__device__ __forceinline__ void mma_bf16(float c[4], const uint32_t a[4],
                                         uint32_t b0, uint32_t b1) {
    asm volatile(
        "mma.sync.aligned.m16n8k16.row.col.f32.bf16.bf16.f32 "
        "{%0,%1,%2,%3},{%4,%5,%6,%7},{%8,%9},{%0,%1,%2,%3};"
        : "+f"(c[0]), "+f"(c[1]), "+f"(c[2]), "+f"(c[3])
        : "r"(a[0]), "r"(a[1]), "r"(a[2]), "r"(a[3]), "r"(b0), "r"(b1));
}
#define CP_ASYNC16(dst, src) \
    asm volatile("cp.async.cg.shared.global [%0], [%1], 16;" :: "r"(dst), "l"(src))
#define CP_COMMIT() asm volatile("cp.async.commit_group;" ::: "memory")
#define CP_WAIT2()  asm volatile("cp.async.wait_group 2;" ::: "memory")
#define SWZ(off) ((off) ^ (((off) >> 3) & 0x70))

// ---------------- init ----------------
__global__ void zero_kernel() {
    int i = blockIdx.x * blockDim.x + threadIdx.x;
    if (i < M_) g_w[i] = 0.0f;
    if (i < B_ * A_) g_count[i] = 0;
}
__global__ void transpose_aw_kernel(const float* __restrict__ aw) {
    int i = blockIdx.x * blockDim.x + threadIdx.x;
    if (i < A_ * H_) {
        int a = i >> 9, k = i & 511;
        g_awT[k * A_ + a] = aw[i];
    }
}
// g_Ah0 = bf16(item+pos), g_Ah1 = bf16(item)
__global__ void prep_kernel(const float* __restrict__ item, const float* __restrict__ pos) {
    int i = blockIdx.x * 256 + threadIdx.x;          // float4 index
    if (i >= M_ * H_ / 4) return;
    int col = (i * 4) & 511;
    int s = ((i * 4) >> 9) % S_;
    float4 v = *(const float4*)&item[i * 4];
    float4 p = *(const float4*)&pos[s * H_ + col];
    uint32_t l0 = pk_bf16x2(v.x, v.y), l1 = pk_bf16x2(v.z, v.w);
    uint32_t h0 = pk_bf16x2(v.x + p.x, v.y + p.y), h1 = pk_bf16x2(v.z + p.z, v.w + p.w);
    *(uint2*)&g_Ah1[i * 4] = make_uint2(l0, l1);
    *(uint2*)&g_Ah0[i * 4] = make_uint2(h0, h1);
}
// transpose + bf16-round the 512x512 weight: g_wTh[n][k] = bf16(W[k][n])
__global__ void transpose_w_kernel(const float* __restrict__ W) {
    __shared__ float ts[32][33];
    int bx = blockIdx.x & 15, by = blockIdx.x >> 4;
    int tx = threadIdx.x & 31, ty = threadIdx.x >> 5;
#pragma unroll
    for (int r = 0; r < 4; r++)
        ts[ty + r * 8][tx] = W[(by * 32 + ty + r * 8) * H_ + bx * 32 + tx];
    __syncthreads();
#pragma unroll
    for (int r = 0; r < 4; r++)
        g_wTh[(bx * 32 + ty + r * 8) * H_ + by * 32 + tx] =
            __float2bfloat16_rn(ts[tx][ty + r * 8]);
}

// ====== bf16 cp.async pipelined GEMM: C[256x128 tile] = A[M,512]@W[512,512] ==
// MODE 0: epilogue leaky(acc+b1)*w2 row-reduce -> atomicAdd g_w.
// MODE 1: epilogue tanh(acc+lin_b)+item -> g_moe.
#define A_BYTES 32768                  // 256 rows x 128B
#define B_BYTES 16384                  // 128 rows x 128B
#define STG_BYTES (A_BYTES + B_BYTES)  // 49152
#define RED_OFF (3 * STG_BYTES)        // 147456
#define SMEM_BYTES (RED_OFF + 1024*4 + 128*4 + 128*4)

template <int MODE>
__global__ void __launch_bounds__(512, 1) gemm6(
    const __nv_bfloat16* __restrict__ Ah, const float* __restrict__ Amat,
    const float* __restrict__ p0g, const float* __restrict__ p1g) {
    extern __shared__ char smem[];
    float* red = (float*)(smem + RED_OFF);        // [4][256]
    float* P0  = red + 1024;
    float* P1  = P0 + 128;

    const int tid = threadIdx.x;
    const int lane = tid & 31;
    const int wid = tid >> 5;
    const int g = lane >> 2, q = lane & 3;
    const int warp_m = wid & 3;            // 0..3 -> 64-row block
    const int warp_n = wid >> 2;           // 0..3 -> 32-col slice
    const int row0 = blockIdx.y * 256;
    const int n0 = blockIdx.x * 128;
    const uint32_t sbase = smem_u32(smem);

    const int lmA = lane & 15;
    const int uhA = lane >> 4;
    const int lmB = (lane & 7) + ((lane >> 4) << 3);
    const int uhB = (lane >> 3) & 1;

    if (tid < 128) {
        P0[tid] = p0g[n0 + tid];
        if (MODE == 0) P1[tid] = p1g[n0 + tid];
    }

    float c[4][4][4];
#pragma unroll
    for (int mf = 0; mf < 4; mf++)
#pragma unroll
        for (int nf = 0; nf < 4; nf++)
#pragma unroll
            for (int i = 0; i < 4; i++) c[mf][nf][i] = 0.0f;

    auto issue = [&](int ch, int st) {
        const int k0 = ch * 64;
        const uint32_t ab = sbase + st * STG_BYTES;
        const uint32_t bb = ab + A_BYTES;
#pragma unroll
        for (int u = 0; u < 4; u++) {
            int un = tid + u * 512;        // 0..2047
            int r = un >> 3, cu = un & 7;
            const void* src = &Ah[(size_t)(row0 + r) * H_ + k0 + cu * 8];
            CP_ASYNC16(ab + SWZ((uint32_t)(r * 128 + cu * 16)), src);
        }
#pragma unroll
        for (int u = 0; u < 2; u++) {
            int un = tid + u * 512;        // 0..1023
            int r = un >> 3, cu = un & 7;
            const void* src = &g_wTh[(size_t)(n0 + r) * H_ + k0 + cu * 8];
            CP_ASYNC16(bb + SWZ((uint32_t)(r * 128 + cu * 16)), src);
        }
    };

    issue(0, 0); CP_COMMIT();
    issue(1, 1); CP_COMMIT();

    const int mb = warp_m * 64;
    const int nb = warp_n * 32;
#pragma unroll 1
    for (int ch = 0; ch < 8; ch++) {
        if (ch + 2 < 8) issue(ch + 2, (ch + 2) % 3);
        CP_COMMIT();
        CP_WAIT2();
        __syncthreads();

        const uint32_t Au = sbase + (ch % 3) * STG_BYTES;
        const uint32_t Bu = Au + A_BYTES;
#pragma unroll
        for (int ks = 0; ks < 4; ks++) {
            uint32_t af[4][4];
#pragma unroll
            for (int mf = 0; mf < 4; mf++) {
                int off = (mb + mf * 16 + lmA) * 128 + (2 * ks + uhA) * 16;
                ldm4(af[mf], Au + SWZ((uint32_t)off));
            }
            uint32_t bfr[2][4];
#pragma unroll
            for (int nh = 0; nh < 2; nh++) {
                int off = (nb + nh * 16 + lmB) * 128 + (2 * ks + uhB) * 16;
                ldm4(bfr[nh], Bu + SWZ((uint32_t)off));
            }
#pragma unroll
            for (int mf = 0; mf < 4; mf++)
#pragma unroll
                for (int nf = 0; nf < 4; nf++)
                    mma_bf16(c[mf][nf], af[mf], bfr[nf >> 1][(nf & 1) * 2],
                             bfr[nf >> 1][(nf & 1) * 2 + 1]);
        }
        __syncthreads();
    }

    if (MODE == 1) {
#pragma unroll
        for (int mf = 0; mf < 4; mf++) {
            int r = row0 + mb + mf * 16 + g;
#pragma unroll
            for (int nf = 0; nf < 4; nf++) {
                int lc = nb + nf * 8 + 2 * q;
                int col = n0 + lc;
                float2 res0 = *(const float2*)&Amat[(size_t)r * H_ + col];
                float2 res1 = *(const float2*)&Amat[(size_t)(r + 8) * H_ + col];
                float2 o0, o1;
                o0.x = tanhf(c[mf][nf][0] + P0[lc]) + res0.x;
                o0.y = tanhf(c[mf][nf][1] + P0[lc + 1]) + res0.y;
                o1.x = tanhf(c[mf][nf][2] + P0[lc]) + res1.x;
                o1.y = tanhf(c[mf][nf][3] + P0[lc + 1]) + res1.y;
                *(float2*)&g_moe[(size_t)r * H_ + col] = o0;
                *(float2*)&g_moe[(size_t)(r + 8) * H_ + col] = o1;
            }
        }
    } else {
        float pr[4][2];
#pragma unroll
        for (int mf = 0; mf < 4; mf++) { pr[mf][0] = 0.0f; pr[mf][1] = 0.0f; }
#pragma unroll
        for (int mf = 0; mf < 4; mf++)
#pragma unroll
            for (int nf = 0; nf < 4; nf++) {
                int lc = nb + nf * 8 + 2 * q;
                float h;
                h = c[mf][nf][0] + P0[lc];     h = (h > 0.f) ? h : 0.01f * h; pr[mf][0] += h * P1[lc];
                h = c[mf][nf][1] + P0[lc + 1]; h = (h > 0.f) ? h : 0.01f * h; pr[mf][0] += h * P1[lc + 1];
                h = c[mf][nf][2] + P0[lc];     h = (h > 0.f) ? h : 0.01f * h; pr[mf][1] += h * P1[lc];
                h = c[mf][nf][3] + P0[lc + 1]; h = (h > 0.f) ? h : 0.01f * h; pr[mf][1] += h * P1[lc + 1];
            }
#pragma unroll
        for (int mf = 0; mf < 4; mf++)
#pragma unroll
            for (int o = 1; o < 4; o <<= 1) {
                pr[mf][0] += __shfl_xor_sync(0xffffffffu, pr[mf][0], o);
                pr[mf][1] += __shfl_xor_sync(0xffffffffu, pr[mf][1], o);
            }
        if (q == 0) {
#pragma unroll
            for (int mf = 0; mf < 4; mf++) {
                red[warp_n * 256 + mb + mf * 16 + g] = pr[mf][0];
                red[warp_n * 256 + mb + mf * 16 + g + 8] = pr[mf][1];
            }
        }
        __syncthreads();
        if (tid < 256) {
            float s = red[tid] + red[256 + tid] + red[512 + tid] + red[768 + tid];
            atomicAdd(&g_w[row0 + tid], s);
        }
    }
}

// ---------------- tma softmax over S per batch ----------------
__global__ void tma_softmax_kernel(const int* __restrict__ seq) {
    int b = blockIdx.x;
    int t = threadIdx.x;
    __shared__ float sd[256];
    float v = -3.4e38f;
    if (t < S_) v = (seq[b * S_ + t] == 0) ? NEGV : g_w[b * S_ + t];
    sd[t] = v;
    __syncthreads();
    for (int o = 128; o; o >>= 1) { if (t < o) sd[t] = fmaxf(sd[t], sd[t + o]); __syncthreads(); }
    float m = sd[0];
    __syncthreads();
    float e = (t < S_) ? expf(v - m) : 0.0f;
    sd[t] = e;
    __syncthreads();
    for (int o = 128; o; o >>= 1) { if (t < o) sd[t] += sd[t + o]; __syncthreads(); }
    float s = sd[0];
    if (t < S_) g_w[b * S_ + t] = e / s;
}

// ---------------- LayerNorm over H, in place on g_moe ----------------
__global__ void ln_kernel(const float* __restrict__ gam, const float* __restrict__ bet) {
    int row = blockIdx.x * 8 + (threadIdx.x >> 5);
    int lane = threadIdx.x & 31;
    float* p = &g_moe[(size_t)row * H_];
    float4 x[4];
    float sum = 0.0f;
#pragma unroll
    for (int q = 0; q < 4; q++) {
        x[q] = *(float4*)&p[lane * 4 + q * 128];
        sum += x[q].x + x[q].y + x[q].z + x[q].w;
    }
    for (int o = 16; o; o >>= 1) sum += __shfl_xor_sync(0xffffffffu, sum, o);
    float mu = sum * (1.0f / H_);
    float sq = 0.0f;
#pragma unroll
    for (int q = 0; q < 4; q++) {
        float a = x[q].x - mu, bb = x[q].y - mu, c = x[q].z - mu, d = x[q].w - mu;
        sq += a * a + bb * bb + c * c + d * d;
    }
    for (int o = 16; o; o >>= 1) sq += __shfl_xor_sync(0xffffffffu, sq, o);
    float rs = rsqrtf(sq * (1.0f / H_) + 1e-12f);
#pragma unroll
    for (int q = 0; q < 4; q++) {
        int col = lane * 4 + q * 128;
        float4 o4;
        o4.x = (x[q].x - mu) * rs * gam[col + 0] + bet[col + 0];
        o4.y = (x[q].y - mu) * rs * gam[col + 1] + bet[col + 1];
        o4.z = (x[q].z - mu) * rs * gam[col + 2] + bet[col + 2];
        o4.w = (x[q].w - mu) * rs * gam[col + 3] + bet[col + 3];
        *(float4*)&p[col] = o4;
    }
}

// ---------------- gates: GEMV x32 + softmax + argmax + scatter count ------
__launch_bounds__(256)
__global__ void gates_kernel(const float* __restrict__ item, const int* __restrict__ seq,
                             float* __restrict__ out_gsm) {
    __shared__ float xs[8][512];
    int tid = threadIdx.x, w = tid >> 5, lane = tid & 31;
    int row = blockIdx.x * 8 + w;
    const float* xr = &item[(size_t)row * H_];
#pragma unroll
    for (int q = 0; q < 16; q++) xs[w][lane + q * 32] = xr[lane + q * 32];
    __syncwarp();
    float acc = 0.0f;
#pragma unroll 4
    for (int k = 0; k < H_; k++) acc += xs[w][k] * g_awT[k * A_ + lane];

    float mv = acc;
    int mi = lane;
    for (int o = 16; o; o >>= 1) {
        float ov = __shfl_xor_sync(0xffffffffu, mv, o);
        int oi = __shfl_xor_sync(0xffffffffu, mi, o);
        if (ov > mv || (ov == mv && oi < mi)) { mv = ov; mi = oi; }
    }
    float e = expf(acc - mv);
    float s = e;
    for (int o = 16; o; o >>= 1) s += __shfl_xor_sync(0xffffffffu, s, o);
    out_gsm[row * A_ + lane] = e / s;
    g_bij[row * A_ + lane] = acc;
    if (lane == 0 && seq[row] != 0) atomicAdd(&g_count[(row / S_) * A_ + mi], 1);
}

__global__ void mask_kernel(float* __restrict__ out_mask) {
    int i = blockIdx.x * blockDim.x + threadIdx.x;
    if (i < B_ * A_) out_mask[i] = (g_count[i] == 0) ? 1.0f : 0.0f;
}

// ==== cap_fused: cijt (softmax*tma) + cap GEMM + squash, one CTA per batch ==
// block 512: phase1 warps build cw[200][32]; phase2 thread j owns column h=j.
__global__ void __launch_bounds__(512, 1) cap_fused(const int* __restrict__ seq,
                                                    float* __restrict__ cap) {
    __shared__ float cw[S_ * A_];          // 25.6KB
    __shared__ float part[A_ * 16];        // warp partials for squash
    __shared__ float scale[A_];
    const int b = blockIdx.x;
    const int tid = threadIdx.x;
    const int wid = tid >> 5, lane = tid & 31;

    // phase 1: cw[s][a] = softmax_a(masked bij) * pad * tma
    const int cnt = g_count[b * A_ + lane];
    for (int s = wid; s < S_; s += 16) {
        const int row = b * S_ + s;
        float v = (cnt == 0) ? NEGV : g_bij[row * A_ + lane];
        float mv = v;
        for (int o = 16; o; o >>= 1) mv = fmaxf(mv, __shfl_xor_sync(0xffffffffu, mv, o));
        float e = expf(v - mv);
        float sum = e;
        for (int o = 16; o; o >>= 1) sum += __shfl_xor_sync(0xffffffffu, sum, o);
        float c = e / sum;
        if (seq[row] == 0) c = 0.0f;
        cw[s * A_ + lane] = c * g_w[row];
    }
    __syncthreads();

    // phase 2: acc[a] = sum_s cw[s][a] * moe[b][s][j]
    float acc[A_];
#pragma unroll
    for (int a = 0; a < A_; a++) acc[a] = 0.0f;
    const float* moeb = &g_moe[(size_t)b * S_ * H_ + tid];
#pragma unroll 2
    for (int s = 0; s < S_; s++) {
        float m = moeb[s * H_];
        const float4* c4 = (const float4*)&cw[s * A_];
#pragma unroll
        for (int a4 = 0; a4 < 8; a4++) {
            float4 cv = c4[a4];
            acc[a4 * 4 + 0] += m * cv.x;
            acc[a4 * 4 + 1] += m * cv.y;
            acc[a4 * 4 + 2] += m * cv.z;
            acc[a4 * 4 + 3] += m * cv.w;
        }
    }

    // squash: n_a = sum_j acc[a]^2
#pragma unroll
    for (int a = 0; a < A_; a++) {
        float v = acc[a] * acc[a];
        for (int o = 16; o; o >>= 1) v += __shfl_xor_sync(0xffffffffu, v, o);
        if (lane == 0) part[a * 16 + wid] = v;
    }
    __syncthreads();
    if (tid < A_) {
        float n = 0.0f;
#pragma unroll
        for (int w = 0; w < 16; w++) n += part[tid * 16 + w];
        scale[tid] = n / ((1.0f + n) * sqrtf(n + 1e-9f));
    }
    __syncthreads();
#pragma unroll
    for (int a = 0; a < A_; a++)
        cap[((size_t)b * A_ + a) * H_ + tid] = acc[a] * scale[a];
}

// ==== bij_fused: bij[s][a] += sum_h moe[s][h]*cap[a][h], one CTA per batch ==
#define CAPS_PAD 516
#define BIJ_SMEM (A_ * CAPS_PAD * 4)
__global__ void __launch_bounds__(512, 1) bij_fused(const float* __restrict__ cap) {
    extern __shared__ float caps[];        // [32][516]
    const int b = blockIdx.x;
    const int tid = threadIdx.x;
    const int wid = tid >> 5, a = tid & 31;

    // stage cap[b] (squashed) into padded smem
    const float4* cap4 = (const float4*)&cap[(size_t)b * A_ * H_];
    for (int i4 = tid; i4 < A_ * (H_ / 4); i4 += 512) {
        int aa = i4 >> 7, h4 = i4 & 127;
        ((float4*)(caps + aa * CAPS_PAD))[h4] = cap4[aa * 128 + h4];
    }
    __syncthreads();

    const float4* capr = (const float4*)(caps + a * CAPS_PAD);
    for (int s = wid; s < S_; s += 16) {
        const int row = b * S_ + s;
        const float4* m4 = (const float4*)&g_moe[(size_t)row * H_];
        float acc = 0.0f;
#pragma unroll 4
        for (int h4 = 0; h4 < 128; h4++) {
            float4 m = m4[h4];
            float4 c = capr[h4];
            acc += m.x * c.x + m.y * c.y + m.z * c.z + m.w * c.w;
        }
        g_bij[row * A_ + a] += acc;
    }
}

// ---------------- host ----------------
extern "C" void kernel_launch(void* const* d_in, const int* in_sizes, int n_in,
                              void* d_out, int out_size) {
    const float* item = (const float*)d_in[0];
    const int*   seq  = (const int*)d_in[1];
    const float* pos  = (const float*)d_in[2];
    const float* w1   = (const float*)d_in[3];
    const float* b1   = (const float*)d_in[4];
    const float* w2   = (const float*)d_in[5];
    // d_in[6] = attn_b2: softmax-invariant constant shift, a no-op
    const float* lw   = (const float*)d_in[7];
    const float* lb   = (const float*)d_in[8];
    const float* aw   = (const float*)d_in[9];
    const float* lng  = (const float*)d_in[10];
    const float* lnb  = (const float*)d_in[11];

    const size_t CAPN = (size_t)B_ * A_ * H_;
    const size_t GSN  = (size_t)M_ * A_;
    const size_t MKN  = (size_t)B_ * A_;

    float* out_cap = (float*)d_out;
    float* out_gsm;
    float* out_mask;
    if ((size_t)out_size >= CAPN + GSN + MKN) {
        out_gsm  = out_cap + CAPN;
        out_mask = out_cap + CAPN + GSN;
    } else {
        void* p;
        cudaGetSymbolAddress(&p, g_dummy_gates); out_gsm = (float*)p;
        cudaGetSymbolAddress(&p, g_dummy_mask);  out_mask = (float*)p;
    }

    cudaFuncSetAttribute(gemm6<0>, cudaFuncAttributeMaxDynamicSharedMemorySize, SMEM_BYTES);
    cudaFuncSetAttribute(gemm6<1>, cudaFuncAttributeMaxDynamicSharedMemorySize, SMEM_BYTES);
    cudaFuncSetAttribute(bij_fused, cudaFuncAttributeMaxDynamicSharedMemorySize, BIJ_SMEM);

    __nv_bfloat16 *ah0, *ah1;
    { void* p;
      cudaGetSymbolAddress(&p, g_Ah0); ah0 = (__nv_bfloat16*)p;
      cudaGetSymbolAddress(&p, g_Ah1); ah1 = (__nv_bfloat16*)p; }

    zero_kernel<<<(M_ + 255) / 256, 256>>>();
    transpose_aw_kernel<<<(A_ * H_ + 255) / 256, 256>>>(aw);
    prep_kernel<<<(M_ * H_ / 4 + 255) / 256, 256>>>(item, pos);

    transpose_w_kernel<<<256, 256>>>(w1);
    gemm6<0><<<dim3(4, 400), 512, SMEM_BYTES>>>(ah0, item, b1, w2);
    tma_softmax_kernel<<<B_, 256>>>(seq);

    transpose_w_kernel<<<256, 256>>>(lw);
    gemm6<1><<<dim3(4, 400), 512, SMEM_BYTES>>>(ah1, item, lb, nullptr);
    ln_kernel<<<M_ / 8, 256>>>(lng, lnb);

    gates_kernel<<<M_ / 8, 256>>>(item, seq, out_gsm);
    mask_kernel<<<(B_ * A_ + 255) / 256, 256>>>(out_mask);

    for (int t = 0; t < 3; t++) {
        cap_fused<<<B_, 512>>>(seq, out_cap);
        if (t < 2) bij_fused<<<B_, 512, BIJ_SMEM>>>(out_cap);
    }
}